// round 2
// baseline (speedup 1.0000x reference)
#include <cuda_runtime.h>
#include <cuda_bf16.h>
#include <cstdint>

#define N_USER 100000
#define N_ITEM 50000
#define N_TOTAL (N_USER + N_ITEM)   // 150000
#define D 64
#define NNZ 4000000
#define B 2048
#define NEG (4 * B)                  // 8192
#define NSLOTS (B + B + NEG)         // 12288

// Scratch: accumulator for ae0 rows (only needed rows are zeroed/used) + flag table.
__device__ float g_acc[(size_t)N_TOTAL * D];           // 38.4 MB
__device__ unsigned char g_needed[N_TOTAL];            // 150 KB

// ---------------------------------------------------------------------------
// K1: clear flag table
// ---------------------------------------------------------------------------
__global__ void k_clear_flags() {
    int i = blockIdx.x * blockDim.x + threadIdx.x;
    if (i < N_TOTAL) g_needed[i] = 0;
}

// slot -> global row id in [0, N_TOTAL)
__device__ __forceinline__ int slot_row(int s, const int* __restrict__ users,
                                        const int* __restrict__ pos,
                                        const int* __restrict__ neg) {
    if (s < B) return users[s];
    if (s < 2 * B) return N_USER + pos[s - B];
    return N_USER + neg[s - 2 * B];
}

// ---------------------------------------------------------------------------
// K2: mark needed rows and zero their accumulator rows (one warp per slot)
// ---------------------------------------------------------------------------
__global__ void k_mark_and_zero(const int* __restrict__ users,
                                const int* __restrict__ pos,
                                const int* __restrict__ neg) {
    int gtid = blockIdx.x * blockDim.x + threadIdx.x;
    int warp = gtid >> 5;
    int lane = gtid & 31;
    if (warp >= NSLOTS) return;
    int r = slot_row(warp, users, pos, neg);
    if (lane == 0) g_needed[r] = 1;
    // zero 64 floats: each lane writes one float2 (duplicates race writing 0.0 — benign)
    float2 z; z.x = 0.0f; z.y = 0.0f;
    reinterpret_cast<float2*>(g_acc + (size_t)r * D)[lane] = z;
}

// ---------------------------------------------------------------------------
// K3: filtered SpMM. One thread per edge checks the flag; hits are processed
// cooperatively by the whole warp (float2 gather + 2 atomicAdds per lane).
// ---------------------------------------------------------------------------
__global__ void k_spmm_filtered(const int* __restrict__ adj_row,
                                const int* __restrict__ adj_col,
                                const float* __restrict__ adj_val,
                                const float* __restrict__ user_emb,
                                const float* __restrict__ item_emb) {
    int i = blockIdx.x * blockDim.x + threadIdx.x;
    int lane = threadIdx.x & 31;

    int r = 0, c = 0;
    float v = 0.0f;
    bool act = false;
    if (i < NNZ) {
        r = adj_row[i];
        act = (g_needed[r] != 0);
    }
    unsigned mask = __ballot_sync(0xffffffffu, act);
    if (act) {
        c = adj_col[i];
        v = adj_val[i];
    }
    while (mask) {
        int b = __ffs(mask) - 1;
        mask &= mask - 1;
        int rr = __shfl_sync(0xffffffffu, r, b);
        int cc = __shfl_sync(0xffffffffu, c, b);
        float vv = __shfl_sync(0xffffffffu, v, b);

        const float* src = (cc < N_USER)
                               ? (user_emb + (size_t)cc * D)
                               : (item_emb + (size_t)(cc - N_USER) * D);
        float2 e = reinterpret_cast<const float2*>(src)[lane];
        float* dst = g_acc + (size_t)rr * D + lane * 2;
        atomicAdd(dst, vv * e.x);
        atomicAdd(dst + 1, vv * e.y);
    }
}

// ---------------------------------------------------------------------------
// K4: final gather: out[slot] = (e0[row] + 3*acc[row]) / 4   (one warp per slot)
// ---------------------------------------------------------------------------
__global__ void k_gather_out(const int* __restrict__ users,
                             const int* __restrict__ pos,
                             const int* __restrict__ neg,
                             const float* __restrict__ user_emb,
                             const float* __restrict__ item_emb,
                             float* __restrict__ out) {
    int gtid = blockIdx.x * blockDim.x + threadIdx.x;
    int warp = gtid >> 5;
    int lane = gtid & 31;
    if (warp >= NSLOTS) return;
    int r = slot_row(warp, users, pos, neg);

    const float* e0 = (r < N_USER) ? (user_emb + (size_t)r * D)
                                   : (item_emb + (size_t)(r - N_USER) * D);
    float2 e = reinterpret_cast<const float2*>(e0)[lane];
    float2 a = reinterpret_cast<const float2*>(g_acc + (size_t)r * D)[lane];
    float2 o;
    o.x = (e.x + 3.0f * a.x) * 0.25f;
    o.y = (e.y + 3.0f * a.y) * 0.25f;
    reinterpret_cast<float2*>(out + (size_t)warp * D)[lane] = o;
}

// ---------------------------------------------------------------------------
// launch
// ---------------------------------------------------------------------------
extern "C" void kernel_launch(void* const* d_in, const int* in_sizes, int n_in,
                              void* d_out, int out_size) {
    const int*   users    = (const int*)d_in[0];
    const int*   pos      = (const int*)d_in[1];
    const int*   neg      = (const int*)d_in[2];
    // d_in[3] mask, d_in[4] norm_adj: unused placeholders
    const float* user_emb = (const float*)d_in[5];
    const float* item_emb = (const float*)d_in[6];
    const int*   adj_row  = (const int*)d_in[7];
    const int*   adj_col  = (const int*)d_in[8];
    const float* adj_val  = (const float*)d_in[9];
    float* out = (float*)d_out;

    (void)in_sizes; (void)n_in; (void)out_size;

    // K1: clear flags
    {
        int threads = 256;
        int blocks = (N_TOTAL + threads - 1) / threads;
        k_clear_flags<<<blocks, threads>>>();
    }
    // K2: mark + zero (one warp per slot)
    {
        int threads = 256;                       // 8 warps/block
        int blocks = (NSLOTS * 32 + threads - 1) / threads;
        k_mark_and_zero<<<blocks, threads>>>(users, pos, neg);
    }
    // K3: filtered SpMM over all edges
    {
        int threads = 256;
        int blocks = (NNZ + threads - 1) / threads;
        k_spmm_filtered<<<blocks, threads>>>(adj_row, adj_col, adj_val,
                                             user_emb, item_emb);
    }
    // K4: gather outputs
    {
        int threads = 256;
        int blocks = (NSLOTS * 32 + threads - 1) / threads;
        k_gather_out<<<blocks, threads>>>(users, pos, neg, user_emb, item_emb, out);
    }
}

// round 3
// speedup vs baseline: 1.2592x; 1.2592x over previous
#include <cuda_runtime.h>
#include <cuda_bf16.h>
#include <cstdint>

#define N_USER 100000
#define N_ITEM 50000
#define N_TOTAL (N_USER + N_ITEM)   // 150000
#define D 64
#define NNZ 4000000
#define B 2048
#define NEG (4 * B)                  // 8192
#define NSLOTS (B + B + NEG)         // 12288
#define NWORDS ((N_TOTAL + 31) / 32) // 4688 words = 18.75 KB bitset

// Scratch: accumulator for ae0 rows (only needed rows touched) + flag bitset.
// __device__ globals are zero-initialized at module load; K4 restores the
// bitset to all-zero each call, so no separate clear kernel is needed.
__device__ float    g_acc[(size_t)N_TOTAL * D];   // 38.4 MB
__device__ unsigned g_flags[NWORDS];              // 18.75 KB (L1-resident)

// slot -> global row id in [0, N_TOTAL)
__device__ __forceinline__ int slot_row(int s, const int* __restrict__ users,
                                        const int* __restrict__ pos,
                                        const int* __restrict__ neg) {
    if (s < B) return users[s];
    if (s < 2 * B) return N_USER + pos[s - B];
    return N_USER + neg[s - 2 * B];
}

// ---------------------------------------------------------------------------
// K2: mark needed rows (bitset) and zero their accumulator rows.
// One warp per slot; duplicate slots race writing identical zeros — benign.
// ---------------------------------------------------------------------------
__global__ void k_mark_and_zero(const int* __restrict__ users,
                                const int* __restrict__ pos,
                                const int* __restrict__ neg) {
    int gtid = blockIdx.x * blockDim.x + threadIdx.x;
    int warp = gtid >> 5;
    int lane = gtid & 31;
    if (warp >= NSLOTS) return;
    int r = slot_row(warp, users, pos, neg);
    if (lane == 0) atomicOr(&g_flags[r >> 5], 1u << (r & 31));
    float2 z; z.x = 0.0f; z.y = 0.0f;
    reinterpret_cast<float2*>(g_acc + (size_t)r * D)[lane] = z;
}

// ---------------------------------------------------------------------------
// K3: filtered SpMM. One thread per edge probes the L1-resident bitset;
// hits are processed two-at-a-time: each half-warp handles one edge with
// float4 gathers and red.global.add.v4.f32 (1 instr per 16B).
// ---------------------------------------------------------------------------
__global__ void k_spmm_filtered(const int* __restrict__ adj_row,
                                const int* __restrict__ adj_col,
                                const float* __restrict__ adj_val,
                                const float* __restrict__ user_emb,
                                const float* __restrict__ item_emb) {
    int i = blockIdx.x * blockDim.x + threadIdx.x;
    int lane = threadIdx.x & 31;
    int half = lane >> 4;          // 0 or 1
    int l    = lane & 15;          // float4 index within row

    int r = 0, c = 0;
    float v = 0.0f;
    bool act = false;
    if (i < NNZ) {
        r = __ldg(adj_row + i);
        act = (g_flags[r >> 5] >> (r & 31)) & 1u;
    }
    unsigned mask = __ballot_sync(0xffffffffu, act);
    if (act) {
        c = __ldg(adj_col + i);
        v = __ldg(adj_val + i);
    }
    while (mask) {
        int b0 = __ffs(mask) - 1; mask &= mask - 1;
        bool have1 = (mask != 0);
        int b1 = b0;
        if (have1) { b1 = __ffs(mask) - 1; mask &= mask - 1; }

        int  b  = half ? b1 : b0;
        int  rr = __shfl_sync(0xffffffffu, r, b);
        int  cc = __shfl_sync(0xffffffffu, c, b);
        float vv = __shfl_sync(0xffffffffu, v, b);

        if (half == 0 || have1) {
            const float* src = (cc < N_USER)
                                   ? (user_emb + (size_t)cc * D)
                                   : (item_emb + (size_t)(cc - N_USER) * D);
            float4 e = __ldg(reinterpret_cast<const float4*>(src) + l);
            float* dst = g_acc + (size_t)rr * D + l * 4;
            asm volatile("red.global.add.v4.f32 [%0], {%1, %2, %3, %4};"
                         :: "l"(dst),
                            "f"(vv * e.x), "f"(vv * e.y),
                            "f"(vv * e.z), "f"(vv * e.w)
                         : "memory");
        }
    }
}

// ---------------------------------------------------------------------------
// K4: out[slot] = (e0[row] + 3*acc[row]) / 4, and clear the flag word so the
// bitset is all-zero again for the next graph replay.
// ---------------------------------------------------------------------------
__global__ void k_gather_out(const int* __restrict__ users,
                             const int* __restrict__ pos,
                             const int* __restrict__ neg,
                             const float* __restrict__ user_emb,
                             const float* __restrict__ item_emb,
                             float* __restrict__ out) {
    int gtid = blockIdx.x * blockDim.x + threadIdx.x;
    int warp = gtid >> 5;
    int lane = gtid & 31;
    if (warp >= NSLOTS) return;
    int r = slot_row(warp, users, pos, neg);

    if (lane == 0) g_flags[r >> 5] = 0u;   // racing stores of 0 — benign

    const float* e0 = (r < N_USER) ? (user_emb + (size_t)r * D)
                                   : (item_emb + (size_t)(r - N_USER) * D);
    float2 e = reinterpret_cast<const float2*>(e0)[lane];
    float2 a = reinterpret_cast<const float2*>(g_acc + (size_t)r * D)[lane];
    float2 o;
    o.x = (e.x + 3.0f * a.x) * 0.25f;
    o.y = (e.y + 3.0f * a.y) * 0.25f;
    reinterpret_cast<float2*>(out + (size_t)warp * D)[lane] = o;
}

// ---------------------------------------------------------------------------
// launch
// ---------------------------------------------------------------------------
extern "C" void kernel_launch(void* const* d_in, const int* in_sizes, int n_in,
                              void* d_out, int out_size) {
    const int*   users    = (const int*)d_in[0];
    const int*   pos      = (const int*)d_in[1];
    const int*   neg      = (const int*)d_in[2];
    // d_in[3] mask, d_in[4] norm_adj: unused placeholders
    const float* user_emb = (const float*)d_in[5];
    const float* item_emb = (const float*)d_in[6];
    const int*   adj_row  = (const int*)d_in[7];
    const int*   adj_col  = (const int*)d_in[8];
    const float* adj_val  = (const float*)d_in[9];
    float* out = (float*)d_out;

    (void)in_sizes; (void)n_in; (void)out_size;

    {   // K2: mark + zero (one warp per slot)
        int threads = 256;
        int blocks = (NSLOTS * 32 + threads - 1) / threads;
        k_mark_and_zero<<<blocks, threads>>>(users, pos, neg);
    }
    {   // K3: filtered SpMM over all edges
        int threads = 256;
        int blocks = (NNZ + threads - 1) / threads;
        k_spmm_filtered<<<blocks, threads>>>(adj_row, adj_col, adj_val,
                                             user_emb, item_emb);
    }
    {   // K4: gather outputs + reset flags
        int threads = 256;
        int blocks = (NSLOTS * 32 + threads - 1) / threads;
        k_gather_out<<<blocks, threads>>>(users, pos, neg, user_emb, item_emb, out);
    }
}